// round 1
// baseline (speedup 1.0000x reference)
#include <cuda_runtime.h>
#include <cuda_bf16.h>
#include <math.h>

// Problem constants
#define BATCH 4
#define SEQ   2048
#define DIM   1024
#define MROWS (BATCH * SEQ)   // 8192 flattened rows for QKV projection

// Scratch (allocation-free rule: __device__ globals)
__device__ float g_q[BATCH * SEQ * DIM];
__device__ float g_k[BATCH * SEQ * DIM];
__device__ float g_v[BATCH * SEQ * DIM];
__device__ float g_sc[(size_t)BATCH * SEQ * SEQ];   // scores -> weights (67 MB)

// Tiling parameters (classic SGEMM)
#define BM 128
#define BN 128
#define BK 8
#define TM 8
#define TN 8
#define NTHREADS 256

// ---------------------------------------------------------------------------
// Kernel 1: QKV projection. C = X @ W, X: [8192,1024], W: [1024,1024].
// blockIdx.z selects which of Wq/Wk/Wv -> g_q/g_k/g_v.
// ---------------------------------------------------------------------------
__global__ __launch_bounds__(NTHREADS)
void sgemm_qkv(const float* __restrict__ X,
               const float* __restrict__ Wq,
               const float* __restrict__ Wk,
               const float* __restrict__ Wv) {
    const int which = blockIdx.z;
    const float* __restrict__ W = (which == 0) ? Wq : (which == 1) ? Wk : Wv;
    float* __restrict__ C = (which == 0) ? g_q : (which == 1) ? g_k : g_v;

    const int K = DIM, N = DIM;
    __shared__ float As[BK][BM];
    __shared__ float Bs[BK][BN];

    const int tid  = threadIdx.x;
    const int row0 = blockIdx.y * BM;
    const int col0 = blockIdx.x * BN;

    const int tr = (tid / 16) * TM;
    const int tc = (tid % 16) * TN;

    // A tile load: 128 rows x 8 k -> one float4 per thread
    const int aRow = tid / 2;
    const int aCol = (tid % 2) * 4;
    // B tile load: 8 k x 128 n -> one float4 per thread
    const int bRow = tid / 32;
    const int bCol = (tid % 32) * 4;

    float acc[TM][TN] = {};
    float ar[TM], br[TN];

    for (int k0 = 0; k0 < K; k0 += BK) {
        float4 a4 = *reinterpret_cast<const float4*>(
            &X[(size_t)(row0 + aRow) * K + k0 + aCol]);
        As[aCol + 0][aRow] = a4.x;
        As[aCol + 1][aRow] = a4.y;
        As[aCol + 2][aRow] = a4.z;
        As[aCol + 3][aRow] = a4.w;
        *reinterpret_cast<float4*>(&Bs[bRow][bCol]) =
            *reinterpret_cast<const float4*>(&W[(size_t)(k0 + bRow) * N + col0 + bCol]);
        __syncthreads();
        #pragma unroll
        for (int kk = 0; kk < BK; kk++) {
            #pragma unroll
            for (int i = 0; i < TM; i++) ar[i] = As[kk][tr + i];
            #pragma unroll
            for (int j = 0; j < TN; j++) br[j] = Bs[kk][tc + j];
            #pragma unroll
            for (int i = 0; i < TM; i++)
                #pragma unroll
                for (int j = 0; j < TN; j++)
                    acc[i][j] += ar[i] * br[j];
        }
        __syncthreads();
    }
    #pragma unroll
    for (int i = 0; i < TM; i++)
        #pragma unroll
        for (int j = 0; j < TN; j++)
            C[(size_t)(row0 + tr + i) * N + col0 + tc + j] = acc[i][j];
}

// ---------------------------------------------------------------------------
// Kernel 2: scores = scale * Q @ K^T  (NT GEMM), per batch.
// Skips tiles strictly above the diagonal (never read by softmax).
// ---------------------------------------------------------------------------
__global__ __launch_bounds__(NTHREADS)
void scores_nt(float scale) {
    const int bx = blockIdx.x;   // k tile
    const int by = blockIdx.y;   // q tile
    if (bx > by) return;         // fully masked tile
    const int b = blockIdx.z;

    const float* __restrict__ Q = g_q + (size_t)b * SEQ * DIM;
    const float* __restrict__ Kd = g_k + (size_t)b * SEQ * DIM;
    float* __restrict__ C = g_sc + (size_t)b * SEQ * SEQ;

    const int Kdim = DIM;
    __shared__ float As[BK][BM];
    __shared__ float Bs[BK][BN];

    const int tid  = threadIdx.x;
    const int row0 = by * BM;
    const int col0 = bx * BN;

    const int tr = (tid / 16) * TM;
    const int tc = (tid % 16) * TN;

    const int aRow = tid / 2;
    const int aCol = (tid % 2) * 4;

    float acc[TM][TN] = {};
    float ar[TM], br[TN];

    for (int k0 = 0; k0 < Kdim; k0 += BK) {
        float4 a4 = *reinterpret_cast<const float4*>(
            &Q[(size_t)(row0 + aRow) * Kdim + k0 + aCol]);
        As[aCol + 0][aRow] = a4.x;
        As[aCol + 1][aRow] = a4.y;
        As[aCol + 2][aRow] = a4.z;
        As[aCol + 3][aRow] = a4.w;
        // B^T tile: Bs[kk][n] = K[(col0+n)][k0+kk]
        float4 b4 = *reinterpret_cast<const float4*>(
            &Kd[(size_t)(col0 + aRow) * Kdim + k0 + aCol]);
        Bs[aCol + 0][aRow] = b4.x;
        Bs[aCol + 1][aRow] = b4.y;
        Bs[aCol + 2][aRow] = b4.z;
        Bs[aCol + 3][aRow] = b4.w;
        __syncthreads();
        #pragma unroll
        for (int kk = 0; kk < BK; kk++) {
            #pragma unroll
            for (int i = 0; i < TM; i++) ar[i] = As[kk][tr + i];
            #pragma unroll
            for (int j = 0; j < TN; j++) br[j] = Bs[kk][tc + j];
            #pragma unroll
            for (int i = 0; i < TM; i++)
                #pragma unroll
                for (int j = 0; j < TN; j++)
                    acc[i][j] += ar[i] * br[j];
        }
        __syncthreads();
    }
    #pragma unroll
    for (int i = 0; i < TM; i++)
        #pragma unroll
        for (int j = 0; j < TN; j++)
            C[(size_t)(row0 + tr + i) * SEQ + col0 + tc + j] = acc[i][j] * scale;
}

// ---------------------------------------------------------------------------
// Kernel 3: causal softmax, one block per row. Writes normalized weights in
// [0..q] and ZEROS in (q..SEQ) so the PV GEMM needs no masking.
// ---------------------------------------------------------------------------
__global__ __launch_bounds__(NTHREADS)
void softmax_causal() {
    const int row = blockIdx.x;        // b*SEQ + q
    const int q = row % SEQ;
    float* __restrict__ p = g_sc + (size_t)row * SEQ;
    const int n = q + 1;
    const int tid = threadIdx.x;

    __shared__ float red[NTHREADS];

    float m = -1e30f;
    for (int i = tid; i < n; i += NTHREADS) m = fmaxf(m, p[i]);
    red[tid] = m;
    __syncthreads();
    for (int s = NTHREADS / 2; s > 0; s >>= 1) {
        if (tid < s) red[tid] = fmaxf(red[tid], red[tid + s]);
        __syncthreads();
    }
    m = red[0];
    __syncthreads();

    float sum = 0.0f;
    for (int i = tid; i < n; i += NTHREADS) {
        float e = __expf(p[i] - m);
        p[i] = e;
        sum += e;
    }
    red[tid] = sum;
    __syncthreads();
    for (int s = NTHREADS / 2; s > 0; s >>= 1) {
        if (tid < s) red[tid] += red[tid + s];
        __syncthreads();
    }
    const float inv = 1.0f / red[0];
    __syncthreads();

    for (int i = tid; i < n; i += NTHREADS) p[i] *= inv;
    for (int i = n + tid; i < SEQ; i += NTHREADS) p[i] = 0.0f;
}

// ---------------------------------------------------------------------------
// Kernel 4: out = weights @ V (NN GEMM), per batch. K-loop truncated at the
// query tile's diagonal (weights beyond are zero).
// ---------------------------------------------------------------------------
__global__ __launch_bounds__(NTHREADS)
void pv_nn(float* __restrict__ out) {
    const int b = blockIdx.z;
    const float* __restrict__ A = g_sc + (size_t)b * SEQ * SEQ;  // [2048,2048]
    const float* __restrict__ Bv = g_v + (size_t)b * SEQ * DIM;  // [2048,1024]
    float* __restrict__ C = out + (size_t)b * SEQ * DIM;

    const int Kfull = SEQ, N = DIM;
    __shared__ float As[BK][BM];
    __shared__ float Bs[BK][BN];

    const int tid  = threadIdx.x;
    const int row0 = blockIdx.y * BM;
    const int col0 = blockIdx.x * BN;
    const int kmax = min(Kfull, row0 + BM);  // causal truncation

    const int tr = (tid / 16) * TM;
    const int tc = (tid % 16) * TN;

    const int aRow = tid / 2;
    const int aCol = (tid % 2) * 4;
    const int bRow = tid / 32;
    const int bCol = (tid % 32) * 4;

    float acc[TM][TN] = {};
    float ar[TM], br[TN];

    for (int k0 = 0; k0 < kmax; k0 += BK) {
        float4 a4 = *reinterpret_cast<const float4*>(
            &A[(size_t)(row0 + aRow) * Kfull + k0 + aCol]);
        As[aCol + 0][aRow] = a4.x;
        As[aCol + 1][aRow] = a4.y;
        As[aCol + 2][aRow] = a4.z;
        As[aCol + 3][aRow] = a4.w;
        *reinterpret_cast<float4*>(&Bs[bRow][bCol]) =
            *reinterpret_cast<const float4*>(&Bv[(size_t)(k0 + bRow) * N + col0 + bCol]);
        __syncthreads();
        #pragma unroll
        for (int kk = 0; kk < BK; kk++) {
            #pragma unroll
            for (int i = 0; i < TM; i++) ar[i] = As[kk][tr + i];
            #pragma unroll
            for (int j = 0; j < TN; j++) br[j] = Bs[kk][tc + j];
            #pragma unroll
            for (int i = 0; i < TM; i++)
                #pragma unroll
                for (int j = 0; j < TN; j++)
                    acc[i][j] += ar[i] * br[j];
        }
        __syncthreads();
    }
    #pragma unroll
    for (int i = 0; i < TM; i++)
        #pragma unroll
        for (int j = 0; j < TN; j++)
            C[(size_t)(row0 + tr + i) * N + col0 + tc + j] = acc[i][j];
}

// ---------------------------------------------------------------------------
extern "C" void kernel_launch(void* const* d_in, const int* in_sizes, int n_in,
                              void* d_out, int out_size) {
    const float* x  = (const float*)d_in[0];
    const float* Wq = (const float*)d_in[1];
    const float* Wk = (const float*)d_in[2];
    const float* Wv = (const float*)d_in[3];
    float* out = (float*)d_out;

    // 1) QKV projections: [8192,1024] x [1024,1024], z selects Wq/Wk/Wv
    {
        dim3 grid(DIM / BN, MROWS / BM, 3);
        sgemm_qkv<<<grid, NTHREADS>>>(x, Wq, Wk, Wv);
    }
    // 2) scores = scale * Q K^T (lower-triangular tiles only)
    {
        const float scale = 1.0f / sqrtf((float)DIM);
        dim3 grid(SEQ / BN, SEQ / BM, BATCH);
        scores_nt<<<grid, NTHREADS>>>(scale);
    }
    // 3) causal softmax per row
    {
        softmax_causal<<<BATCH * SEQ, NTHREADS>>>();
    }
    // 4) out = weights @ V (K-loop truncated by causality)
    {
        dim3 grid(DIM / BN, SEQ / BM, BATCH);
        pv_nn<<<grid, NTHREADS>>>(out);
    }
}

// round 2
// speedup vs baseline: 2.7111x; 2.7111x over previous
#include <cuda_runtime.h>
#include <cuda_bf16.h>
#include <math.h>
#include <stdint.h>

#define BATCH 4
#define SEQ   2048
#define DIM   1024
#define MROWS (BATCH * SEQ)

// Scratch
__device__ float g_q[BATCH * SEQ * DIM];
__device__ float g_k[BATCH * SEQ * DIM];
__device__ float g_v[BATCH * SEQ * DIM];
__device__ float g_sc[(size_t)BATCH * SEQ * SEQ];

#define BM 128
#define BN 128
#define BK 16
#define PAD 4
#define NTHREADS 256

// ---------------------------------------------------------------------------
// tf32 helpers
// ---------------------------------------------------------------------------
__device__ __forceinline__ float f2tf32(float f) {
    uint32_t u;
    asm("cvt.rna.tf32.f32 %0, %1;" : "=r"(u) : "f"(f));
    return __uint_as_float(u);
}

__device__ __forceinline__ void mma_tf32(float c[4], const uint32_t a[4],
                                         const uint32_t b[2]) {
    asm volatile(
        "mma.sync.aligned.m16n8k8.row.col.f32.tf32.tf32.f32 "
        "{%0,%1,%2,%3}, {%4,%5,%6,%7}, {%8,%9}, {%0,%1,%2,%3};"
        : "+f"(c[0]), "+f"(c[1]), "+f"(c[2]), "+f"(c[3])
        : "r"(a[0]), "r"(a[1]), "r"(a[2]), "r"(a[3]), "r"(b[0]), "r"(b[1]));
}

// Shared-memory compute core: 8 warps, warp tile 64(m) x 32(n), mma m16n8k8.
// As[k][m], Bs[k][n]; accumulate into c[4][4][4].
__device__ __forceinline__ void mma_tile_compute(
    const float As[BK][BM + PAD], const float Bs[BK][BN + PAD],
    float c[4][4][4], int lane, int warpM, int warpN) {
    #pragma unroll
    for (int ks = 0; ks < BK; ks += 8) {
        uint32_t a[4][4];
        #pragma unroll
        for (int mt = 0; mt < 4; mt++) {
            const int m0 = warpM * 64 + mt * 16 + (lane >> 2);
            const int k0 = ks + (lane & 3);
            a[mt][0] = __float_as_uint(As[k0][m0]);
            a[mt][1] = __float_as_uint(As[k0][m0 + 8]);
            a[mt][2] = __float_as_uint(As[k0 + 4][m0]);
            a[mt][3] = __float_as_uint(As[k0 + 4][m0 + 8]);
        }
        uint32_t b[4][2];
        #pragma unroll
        for (int nt = 0; nt < 4; nt++) {
            const int n0 = warpN * 32 + nt * 8 + (lane >> 2);
            const int k0 = ks + (lane & 3);
            b[nt][0] = __float_as_uint(Bs[k0][n0]);
            b[nt][1] = __float_as_uint(Bs[k0 + 4][n0]);
        }
        #pragma unroll
        for (int mt = 0; mt < 4; mt++)
            #pragma unroll
            for (int nt = 0; nt < 4; nt++)
                mma_tf32(c[mt][nt], a[mt], b[nt]);
    }
}

// ---------------------------------------------------------------------------
// Kernel 1: QKV projection (NN GEMM). C = X @ W; z selects W/output.
// ---------------------------------------------------------------------------
__global__ __launch_bounds__(NTHREADS)
void mm_qkv(const float* __restrict__ X, const float* __restrict__ Wq,
            const float* __restrict__ Wk, const float* __restrict__ Wv) {
    const int which = blockIdx.z;
    const float* __restrict__ W = (which == 0) ? Wq : (which == 1) ? Wk : Wv;
    float* __restrict__ C = (which == 0) ? g_q : (which == 1) ? g_k : g_v;
    const int K = DIM, N = DIM;

    __shared__ float As[BK][BM + PAD];
    __shared__ float Bs[BK][BN + PAD];

    const int tid = threadIdx.x, lane = tid & 31, warp = tid >> 5;
    const int warpM = warp >> 2, warpN = warp & 3;
    const int row0 = blockIdx.y * BM, col0 = blockIdx.x * BN;

    float c[4][4][4] = {};
    float4 pa[2], pb[2];

    // prefetch first tiles
    #pragma unroll
    for (int it = 0; it < 2; it++) {
        int idx = tid + it * 256;
        pa[it] = *reinterpret_cast<const float4*>(
            &X[(size_t)(row0 + (idx >> 2)) * K + (idx & 3) * 4]);
        pb[it] = *reinterpret_cast<const float4*>(
            &W[(size_t)(idx >> 5) * N + col0 + (idx & 31) * 4]);
    }

    for (int k0 = 0; k0 < K; k0 += BK) {
        __syncthreads();
        #pragma unroll
        for (int it = 0; it < 2; it++) {
            int idx = tid + it * 256;
            int r = idx >> 2, cv = (idx & 3) * 4;
            As[cv + 0][r] = f2tf32(pa[it].x);
            As[cv + 1][r] = f2tf32(pa[it].y);
            As[cv + 2][r] = f2tf32(pa[it].z);
            As[cv + 3][r] = f2tf32(pa[it].w);
            int kr = idx >> 5, nv = (idx & 31) * 4;
            float4 t;
            t.x = f2tf32(pb[it].x); t.y = f2tf32(pb[it].y);
            t.z = f2tf32(pb[it].z); t.w = f2tf32(pb[it].w);
            *reinterpret_cast<float4*>(&Bs[kr][nv]) = t;
        }
        __syncthreads();
        if (k0 + BK < K) {
            #pragma unroll
            for (int it = 0; it < 2; it++) {
                int idx = tid + it * 256;
                pa[it] = *reinterpret_cast<const float4*>(
                    &X[(size_t)(row0 + (idx >> 2)) * K + k0 + BK + (idx & 3) * 4]);
                pb[it] = *reinterpret_cast<const float4*>(
                    &W[(size_t)(k0 + BK + (idx >> 5)) * N + col0 + (idx & 31) * 4]);
            }
        }
        mma_tile_compute(As, Bs, c, lane, warpM, warpN);
    }

    #pragma unroll
    for (int mt = 0; mt < 4; mt++)
        #pragma unroll
        for (int nt = 0; nt < 4; nt++) {
            int r = row0 + warpM * 64 + mt * 16 + (lane >> 2);
            int cc = col0 + warpN * 32 + nt * 8 + (lane & 3) * 2;
            *reinterpret_cast<float2*>(&C[(size_t)r * N + cc]) =
                make_float2(c[mt][nt][0], c[mt][nt][1]);
            *reinterpret_cast<float2*>(&C[(size_t)(r + 8) * N + cc]) =
                make_float2(c[mt][nt][2], c[mt][nt][3]);
        }
}

// ---------------------------------------------------------------------------
// Kernel 2: scores = scale * Q @ K^T (NT), lower-triangular tiles only.
// ---------------------------------------------------------------------------
__global__ __launch_bounds__(NTHREADS)
void mm_scores(float scale) {
    const int bx = blockIdx.x, by = blockIdx.y;
    if (bx > by) return;
    const int b = blockIdx.z;
    const float* __restrict__ Q  = g_q + (size_t)b * SEQ * DIM;
    const float* __restrict__ Km = g_k + (size_t)b * SEQ * DIM;
    float* __restrict__ C = g_sc + (size_t)b * SEQ * SEQ;
    const int K = DIM;

    __shared__ float As[BK][BM + PAD];
    __shared__ float Bs[BK][BN + PAD];

    const int tid = threadIdx.x, lane = tid & 31, warp = tid >> 5;
    const int warpM = warp >> 2, warpN = warp & 3;
    const int row0 = by * BM, col0 = bx * BN;

    float c[4][4][4] = {};
    float4 pa[2], pb[2];

    #pragma unroll
    for (int it = 0; it < 2; it++) {
        int idx = tid + it * 256;
        pa[it] = *reinterpret_cast<const float4*>(
            &Q[(size_t)(row0 + (idx >> 2)) * K + (idx & 3) * 4]);
        pb[it] = *reinterpret_cast<const float4*>(
            &Km[(size_t)(col0 + (idx >> 2)) * K + (idx & 3) * 4]);
    }

    for (int k0 = 0; k0 < K; k0 += BK) {
        __syncthreads();
        #pragma unroll
        for (int it = 0; it < 2; it++) {
            int idx = tid + it * 256;
            int r = idx >> 2, cv = (idx & 3) * 4;
            As[cv + 0][r] = f2tf32(pa[it].x);
            As[cv + 1][r] = f2tf32(pa[it].y);
            As[cv + 2][r] = f2tf32(pa[it].z);
            As[cv + 3][r] = f2tf32(pa[it].w);
            // B^T: Bs[k][n] = Km[col0+n][k]
            Bs[cv + 0][r] = f2tf32(pb[it].x);
            Bs[cv + 1][r] = f2tf32(pb[it].y);
            Bs[cv + 2][r] = f2tf32(pb[it].z);
            Bs[cv + 3][r] = f2tf32(pb[it].w);
        }
        __syncthreads();
        if (k0 + BK < K) {
            #pragma unroll
            for (int it = 0; it < 2; it++) {
                int idx = tid + it * 256;
                pa[it] = *reinterpret_cast<const float4*>(
                    &Q[(size_t)(row0 + (idx >> 2)) * K + k0 + BK + (idx & 3) * 4]);
                pb[it] = *reinterpret_cast<const float4*>(
                    &Km[(size_t)(col0 + (idx >> 2)) * K + k0 + BK + (idx & 3) * 4]);
            }
        }
        mma_tile_compute(As, Bs, c, lane, warpM, warpN);
    }

    #pragma unroll
    for (int mt = 0; mt < 4; mt++)
        #pragma unroll
        for (int nt = 0; nt < 4; nt++) {
            int r = row0 + warpM * 64 + mt * 16 + (lane >> 2);
            int cc = col0 + warpN * 32 + nt * 8 + (lane & 3) * 2;
            *reinterpret_cast<float2*>(&C[(size_t)r * SEQ + cc]) =
                make_float2(c[mt][nt][0] * scale, c[mt][nt][1] * scale);
            *reinterpret_cast<float2*>(&C[(size_t)(r + 8) * SEQ + cc]) =
                make_float2(c[mt][nt][2] * scale, c[mt][nt][3] * scale);
        }
}

// ---------------------------------------------------------------------------
// Kernel 3: causal softmax, one block per row; zeros masked tail.
// ---------------------------------------------------------------------------
__global__ __launch_bounds__(NTHREADS)
void softmax_causal() {
    const int row = blockIdx.x;
    const int q = row & (SEQ - 1);
    float* __restrict__ p = g_sc + (size_t)row * SEQ;
    const int n = q + 1;
    const int tid = threadIdx.x, lane = tid & 31, warp = tid >> 5;
    __shared__ float red[8];

    float m = -1e30f;
    for (int i = tid; i < n; i += NTHREADS) m = fmaxf(m, p[i]);
    #pragma unroll
    for (int o = 16; o > 0; o >>= 1) m = fmaxf(m, __shfl_xor_sync(~0u, m, o));
    if (lane == 0) red[warp] = m;
    __syncthreads();
    m = red[lane & 7];
    #pragma unroll
    for (int o = 4; o > 0; o >>= 1) m = fmaxf(m, __shfl_xor_sync(~0u, m, o));

    float sum = 0.0f;
    for (int i = tid; i < n; i += NTHREADS) {
        float e = __expf(p[i] - m);
        p[i] = e;
        sum += e;
    }
    #pragma unroll
    for (int o = 16; o > 0; o >>= 1) sum += __shfl_xor_sync(~0u, sum, o);
    __syncthreads();
    if (lane == 0) red[warp] = sum;
    __syncthreads();
    sum = red[lane & 7];
    #pragma unroll
    for (int o = 4; o > 0; o >>= 1) sum += __shfl_xor_sync(~0u, sum, o);
    const float inv = 1.0f / sum;

    for (int i = tid; i < n; i += NTHREADS) p[i] *= inv;
    for (int i = n + tid; i < SEQ; i += NTHREADS) p[i] = 0.0f;
}

// ---------------------------------------------------------------------------
// Kernel 4: out = weights @ V (NN), K-loop truncated by causality.
// ---------------------------------------------------------------------------
__global__ __launch_bounds__(NTHREADS)
void mm_pv(float* __restrict__ out) {
    const int b = blockIdx.z;
    const float* __restrict__ A  = g_sc + (size_t)b * SEQ * SEQ;
    const float* __restrict__ Bv = g_v + (size_t)b * SEQ * DIM;
    float* __restrict__ C = out + (size_t)b * SEQ * DIM;
    const int K = SEQ, N = DIM;

    __shared__ float As[BK][BM + PAD];
    __shared__ float Bs[BK][BN + PAD];

    const int tid = threadIdx.x, lane = tid & 31, warp = tid >> 5;
    const int warpM = warp >> 2, warpN = warp & 3;
    const int row0 = blockIdx.y * BM, col0 = blockIdx.x * BN;
    const int kmax = row0 + BM;  // weights zero beyond the diagonal tile

    float c[4][4][4] = {};
    float4 pa[2], pb[2];

    #pragma unroll
    for (int it = 0; it < 2; it++) {
        int idx = tid + it * 256;
        pa[it] = *reinterpret_cast<const float4*>(
            &A[(size_t)(row0 + (idx >> 2)) * K + (idx & 3) * 4]);
        pb[it] = *reinterpret_cast<const float4*>(
            &Bv[(size_t)(idx >> 5) * N + col0 + (idx & 31) * 4]);
    }

    for (int k0 = 0; k0 < kmax; k0 += BK) {
        __syncthreads();
        #pragma unroll
        for (int it = 0; it < 2; it++) {
            int idx = tid + it * 256;
            int r = idx >> 2, cv = (idx & 3) * 4;
            As[cv + 0][r] = f2tf32(pa[it].x);
            As[cv + 1][r] = f2tf32(pa[it].y);
            As[cv + 2][r] = f2tf32(pa[it].z);
            As[cv + 3][r] = f2tf32(pa[it].w);
            int kr = idx >> 5, nv = (idx & 31) * 4;
            float4 t;
            t.x = f2tf32(pb[it].x); t.y = f2tf32(pb[it].y);
            t.z = f2tf32(pb[it].z); t.w = f2tf32(pb[it].w);
            *reinterpret_cast<float4*>(&Bs[kr][nv]) = t;
        }
        __syncthreads();
        if (k0 + BK < kmax) {
            #pragma unroll
            for (int it = 0; it < 2; it++) {
                int idx = tid + it * 256;
                pa[it] = *reinterpret_cast<const float4*>(
                    &A[(size_t)(row0 + (idx >> 2)) * K + k0 + BK + (idx & 3) * 4]);
                pb[it] = *reinterpret_cast<const float4*>(
                    &Bv[(size_t)(k0 + BK + (idx >> 5)) * N + col0 + (idx & 31) * 4]);
            }
        }
        mma_tile_compute(As, Bs, c, lane, warpM, warpN);
    }

    #pragma unroll
    for (int mt = 0; mt < 4; mt++)
        #pragma unroll
        for (int nt = 0; nt < 4; nt++) {
            int r = row0 + warpM * 64 + mt * 16 + (lane >> 2);
            int cc = col0 + warpN * 32 + nt * 8 + (lane & 3) * 2;
            *reinterpret_cast<float2*>(&C[(size_t)r * N + cc]) =
                make_float2(c[mt][nt][0], c[mt][nt][1]);
            *reinterpret_cast<float2*>(&C[(size_t)(r + 8) * N + cc]) =
                make_float2(c[mt][nt][2], c[mt][nt][3]);
        }
}

// ---------------------------------------------------------------------------
extern "C" void kernel_launch(void* const* d_in, const int* in_sizes, int n_in,
                              void* d_out, int out_size) {
    const float* x  = (const float*)d_in[0];
    const float* Wq = (const float*)d_in[1];
    const float* Wk = (const float*)d_in[2];
    const float* Wv = (const float*)d_in[3];
    float* out = (float*)d_out;

    {
        dim3 grid(DIM / BN, MROWS / BM, 3);
        mm_qkv<<<grid, NTHREADS>>>(x, Wq, Wk, Wv);
    }
    {
        const float scale = 1.0f / sqrtf((float)DIM);
        dim3 grid(SEQ / BN, SEQ / BM, BATCH);
        mm_scores<<<grid, NTHREADS>>>(scale);
    }
    softmax_causal<<<BATCH * SEQ, NTHREADS>>>();
    {
        dim3 grid(DIM / BN, SEQ / BM, BATCH);
        mm_pv<<<grid, NTHREADS>>>(out);
    }
}

// round 3
// speedup vs baseline: 3.0906x; 1.1400x over previous
#include <cuda_runtime.h>
#include <cuda_bf16.h>
#include <math.h>
#include <stdint.h>

#define BATCH 4
#define SEQ   2048
#define DIM   1024
#define MROWS (BATCH * SEQ)

__device__ float g_q[BATCH * SEQ * DIM];
__device__ float g_k[BATCH * SEQ * DIM];
__device__ float g_v[BATCH * SEQ * DIM];
__device__ float g_sc[(size_t)BATCH * SEQ * SEQ];

#define BM 128
#define BN 256
#define BK 16
#define NTHREADS 256

// ---------------------------------------------------------------------------
// tf32 helpers
// ---------------------------------------------------------------------------
__device__ __forceinline__ float f2tf32(float f) {
    uint32_t u;
    asm("cvt.rna.tf32.f32 %0, %1;" : "=r"(u) : "f"(f));
    return __uint_as_float(u);
}

__device__ __forceinline__ void mma_tf32(float c[4], const uint32_t a[4],
                                         const uint32_t b[2]) {
    asm volatile(
        "mma.sync.aligned.m16n8k8.row.col.f32.tf32.tf32.f32 "
        "{%0,%1,%2,%3}, {%4,%5,%6,%7}, {%8,%9}, {%0,%1,%2,%3};"
        : "+f"(c[0]), "+f"(c[1]), "+f"(c[2]), "+f"(c[3])
        : "r"(a[0]), "r"(a[1]), "r"(a[2]), "r"(a[3]), "r"(b[0]), "r"(b[1]));
}

// XOR-swizzled smem layouts (conflict-free for both STS patterns and
// fragment LDS patterns; verified bank math by hand).
__device__ __forceinline__ int aswz(int k, int m) {
    return k * BM + (m ^ (((k & 3) ^ (k >> 2)) << 3));
}
__device__ __forceinline__ int bswz(int k, int n) {
    return k * BN + (n ^ (((k & 3) ^ (k >> 2)) << 3));
}

// Compute core: 8 warps as 2(M) x 4(N); warp tile 64x64; mma m16n8k8 tf32.
__device__ __forceinline__ void mma_tile_compute(
    const float* __restrict__ As, const float* __restrict__ Bs,
    float c[4][8][4], int lane, int warpM, int warpN) {
    #pragma unroll
    for (int ks = 0; ks < BK; ks += 8) {
        const int k0 = ks + (lane & 3);
        uint32_t a[4][4];
        #pragma unroll
        for (int mt = 0; mt < 4; mt++) {
            const int m0 = warpM * 64 + mt * 16 + (lane >> 2);
            a[mt][0] = __float_as_uint(As[aswz(k0, m0)]);
            a[mt][1] = __float_as_uint(As[aswz(k0, m0 + 8)]);
            a[mt][2] = __float_as_uint(As[aswz(k0 + 4, m0)]);
            a[mt][3] = __float_as_uint(As[aswz(k0 + 4, m0 + 8)]);
        }
        uint32_t b[8][2];
        #pragma unroll
        for (int nt = 0; nt < 8; nt++) {
            const int n0 = warpN * 64 + nt * 8 + (lane >> 2);
            b[nt][0] = __float_as_uint(Bs[bswz(k0, n0)]);
            b[nt][1] = __float_as_uint(Bs[bswz(k0 + 4, n0)]);
        }
        #pragma unroll
        for (int mt = 0; mt < 4; mt++)
            #pragma unroll
            for (int nt = 0; nt < 8; nt++)
                mma_tf32(c[mt][nt], a[mt], b[nt]);
    }
}

// Store A-style tile (rows x BK, float4 along k) into swizzled As.
__device__ __forceinline__ void stsA(float* As, const float4* pa, int tid) {
    #pragma unroll
    for (int it = 0; it < 2; it++) {
        const int idx = tid + it * 256;
        const int r = idx >> 2, kc = (idx & 3) * 4;
        As[aswz(kc + 0, r)] = f2tf32(pa[it].x);
        As[aswz(kc + 1, r)] = f2tf32(pa[it].y);
        As[aswz(kc + 2, r)] = f2tf32(pa[it].z);
        As[aswz(kc + 3, r)] = f2tf32(pa[it].w);
    }
}

// ---------------------------------------------------------------------------
// Kernel 1: QKV projection (NN). C = X @ W; z selects W/output.
// ---------------------------------------------------------------------------
__global__ __launch_bounds__(NTHREADS)
void mm_qkv(const float* __restrict__ X, const float* __restrict__ Wq,
            const float* __restrict__ Wk, const float* __restrict__ Wv) {
    const int which = blockIdx.z;
    const float* __restrict__ W = (which == 0) ? Wq : (which == 1) ? Wk : Wv;
    float* __restrict__ C = (which == 0) ? g_q : (which == 1) ? g_k : g_v;
    const int K = DIM, N = DIM;

    __shared__ float As[BK * BM];
    __shared__ float Bs[BK * BN];

    const int tid = threadIdx.x, lane = tid & 31, warp = tid >> 5;
    const int warpM = warp >> 2, warpN = warp & 3;
    const int row0 = blockIdx.y * BM, col0 = blockIdx.x * BN;

    float c[4][8][4] = {};
    float4 pa[2], pb[4];

    #pragma unroll
    for (int it = 0; it < 2; it++) {
        int idx = tid + it * 256;
        pa[it] = *reinterpret_cast<const float4*>(
            &X[(size_t)(row0 + (idx >> 2)) * K + (idx & 3) * 4]);
    }
    #pragma unroll
    for (int it = 0; it < 4; it++) {
        int idx = tid + it * 256;
        pb[it] = *reinterpret_cast<const float4*>(
            &W[(size_t)(idx >> 6) * N + col0 + (idx & 63) * 4]);
    }

    for (int k0 = 0; k0 < K; k0 += BK) {
        __syncthreads();
        stsA(As, pa, tid);
        #pragma unroll
        for (int it = 0; it < 4; it++) {
            int idx = tid + it * 256;
            int kr = idx >> 6, nv = (idx & 63) * 4;
            float4 t;
            t.x = f2tf32(pb[it].x); t.y = f2tf32(pb[it].y);
            t.z = f2tf32(pb[it].z); t.w = f2tf32(pb[it].w);
            *reinterpret_cast<float4*>(&Bs[bswz(kr, nv)]) = t;
        }
        __syncthreads();
        if (k0 + BK < K) {
            #pragma unroll
            for (int it = 0; it < 2; it++) {
                int idx = tid + it * 256;
                pa[it] = *reinterpret_cast<const float4*>(
                    &X[(size_t)(row0 + (idx >> 2)) * K + k0 + BK + (idx & 3) * 4]);
            }
            #pragma unroll
            for (int it = 0; it < 4; it++) {
                int idx = tid + it * 256;
                pb[it] = *reinterpret_cast<const float4*>(
                    &W[(size_t)(k0 + BK + (idx >> 6)) * N + col0 + (idx & 63) * 4]);
            }
        }
        mma_tile_compute(As, Bs, c, lane, warpM, warpN);
    }

    #pragma unroll
    for (int mt = 0; mt < 4; mt++)
        #pragma unroll
        for (int nt = 0; nt < 8; nt++) {
            int r = row0 + warpM * 64 + mt * 16 + (lane >> 2);
            int cc = col0 + warpN * 64 + nt * 8 + (lane & 3) * 2;
            *reinterpret_cast<float2*>(&C[(size_t)r * N + cc]) =
                make_float2(c[mt][nt][0], c[mt][nt][1]);
            *reinterpret_cast<float2*>(&C[(size_t)(r + 8) * N + cc]) =
                make_float2(c[mt][nt][2], c[mt][nt][3]);
        }
}

// ---------------------------------------------------------------------------
// Kernel 2: scores = scale * Q @ K^T (NT), lower-triangular tiles only.
// ---------------------------------------------------------------------------
__global__ __launch_bounds__(NTHREADS)
void mm_scores(float scale) {
    const int bx = blockIdx.x, by = blockIdx.y;
    if (2 * bx > by) return;  // tile cols start beyond tile rows' diagonal
    const int b = blockIdx.z;
    const float* __restrict__ Q  = g_q + (size_t)b * SEQ * DIM;
    const float* __restrict__ Km = g_k + (size_t)b * SEQ * DIM;
    float* __restrict__ C = g_sc + (size_t)b * SEQ * SEQ;
    const int K = DIM;

    __shared__ float As[BK * BM];
    __shared__ float Bs[BK * BN];

    const int tid = threadIdx.x, lane = tid & 31, warp = tid >> 5;
    const int warpM = warp >> 2, warpN = warp & 3;
    const int row0 = by * BM, col0 = bx * BN;

    float c[4][8][4] = {};
    float4 pa[2], pb[4];

    #pragma unroll
    for (int it = 0; it < 2; it++) {
        int idx = tid + it * 256;
        pa[it] = *reinterpret_cast<const float4*>(
            &Q[(size_t)(row0 + (idx >> 2)) * K + (idx & 3) * 4]);
    }
    #pragma unroll
    for (int it = 0; it < 4; it++) {
        int idx = tid + it * 256;
        pb[it] = *reinterpret_cast<const float4*>(
            &Km[(size_t)(col0 + (idx >> 2)) * K + (idx & 3) * 4]);
    }

    for (int k0 = 0; k0 < K; k0 += BK) {
        __syncthreads();
        stsA(As, pa, tid);
        #pragma unroll
        for (int it = 0; it < 4; it++) {
            int idx = tid + it * 256;
            int r = idx >> 2, kc = (idx & 3) * 4;  // r = n index, kc = k
            Bs[bswz(kc + 0, r)] = f2tf32(pb[it].x);
            Bs[bswz(kc + 1, r)] = f2tf32(pb[it].y);
            Bs[bswz(kc + 2, r)] = f2tf32(pb[it].z);
            Bs[bswz(kc + 3, r)] = f2tf32(pb[it].w);
        }
        __syncthreads();
        if (k0 + BK < K) {
            #pragma unroll
            for (int it = 0; it < 2; it++) {
                int idx = tid + it * 256;
                pa[it] = *reinterpret_cast<const float4*>(
                    &Q[(size_t)(row0 + (idx >> 2)) * K + k0 + BK + (idx & 3) * 4]);
            }
            #pragma unroll
            for (int it = 0; it < 4; it++) {
                int idx = tid + it * 256;
                pb[it] = *reinterpret_cast<const float4*>(
                    &Km[(size_t)(col0 + (idx >> 2)) * K + k0 + BK + (idx & 3) * 4]);
            }
        }
        mma_tile_compute(As, Bs, c, lane, warpM, warpN);
    }

    #pragma unroll
    for (int mt = 0; mt < 4; mt++)
        #pragma unroll
        for (int nt = 0; nt < 8; nt++) {
            int r = row0 + warpM * 64 + mt * 16 + (lane >> 2);
            int cc = col0 + warpN * 64 + nt * 8 + (lane & 3) * 2;
            *reinterpret_cast<float2*>(&C[(size_t)r * SEQ + cc]) =
                make_float2(c[mt][nt][0] * scale, c[mt][nt][1] * scale);
            *reinterpret_cast<float2*>(&C[(size_t)(r + 8) * SEQ + cc]) =
                make_float2(c[mt][nt][2] * scale, c[mt][nt][3] * scale);
        }
}

// ---------------------------------------------------------------------------
// Kernel 3: causal softmax; zeros only up to end of own 128-row block
// (PV truncates its K-loop there).
// ---------------------------------------------------------------------------
__global__ __launch_bounds__(NTHREADS)
void softmax_causal() {
    const int row = blockIdx.x;
    const int q = row & (SEQ - 1);
    float* __restrict__ p = g_sc + (size_t)row * SEQ;
    const int n = q + 1;
    const int limit = (q & ~127) + 128;
    const int tid = threadIdx.x, lane = tid & 31, warp = tid >> 5;
    __shared__ float red[8];

    float m = -1e30f;
    for (int i = tid; i < n; i += NTHREADS) m = fmaxf(m, p[i]);
    #pragma unroll
    for (int o = 16; o > 0; o >>= 1) m = fmaxf(m, __shfl_xor_sync(~0u, m, o));
    if (lane == 0) red[warp] = m;
    __syncthreads();
    m = red[lane & 7];
    #pragma unroll
    for (int o = 4; o > 0; o >>= 1) m = fmaxf(m, __shfl_xor_sync(~0u, m, o));

    float sum = 0.0f;
    for (int i = tid; i < n; i += NTHREADS) {
        float e = __expf(p[i] - m);
        p[i] = e;
        sum += e;
    }
    #pragma unroll
    for (int o = 16; o > 0; o >>= 1) sum += __shfl_xor_sync(~0u, sum, o);
    __syncthreads();
    if (lane == 0) red[warp] = sum;
    __syncthreads();
    sum = red[lane & 7];
    #pragma unroll
    for (int o = 4; o > 0; o >>= 1) sum += __shfl_xor_sync(~0u, sum, o);
    const float inv = 1.0f / sum;

    for (int i = tid; i < n; i += NTHREADS) p[i] *= inv;
    for (int i = n + tid; i < limit; i += NTHREADS) p[i] = 0.0f;
}

// ---------------------------------------------------------------------------
// Kernel 4: out = weights @ V (NN), K-loop truncated by causality.
// ---------------------------------------------------------------------------
__global__ __launch_bounds__(NTHREADS)
void mm_pv(float* __restrict__ out) {
    const int b = blockIdx.z;
    const float* __restrict__ A  = g_sc + (size_t)b * SEQ * SEQ;
    const float* __restrict__ Bv = g_v + (size_t)b * SEQ * DIM;
    float* __restrict__ C = out + (size_t)b * SEQ * DIM;
    const int K = SEQ, N = DIM;

    __shared__ float As[BK * BM];
    __shared__ float Bs[BK * BN];

    const int tid = threadIdx.x, lane = tid & 31, warp = tid >> 5;
    const int warpM = warp >> 2, warpN = warp & 3;
    const int row0 = blockIdx.y * BM, col0 = blockIdx.x * BN;
    const int kmax = row0 + BM;

    float c[4][8][4] = {};
    float4 pa[2], pb[4];

    #pragma unroll
    for (int it = 0; it < 2; it++) {
        int idx = tid + it * 256;
        pa[it] = *reinterpret_cast<const float4*>(
            &A[(size_t)(row0 + (idx >> 2)) * K + (idx & 3) * 4]);
    }
    #pragma unroll
    for (int it = 0; it < 4; it++) {
        int idx = tid + it * 256;
        pb[it] = *reinterpret_cast<const float4*>(
            &Bv[(size_t)(idx >> 6) * N + col0 + (idx & 63) * 4]);
    }

    for (int k0 = 0; k0 < kmax; k0 += BK) {
        __syncthreads();
        stsA(As, pa, tid);
        #pragma unroll
        for (int it = 0; it < 4; it++) {
            int idx = tid + it * 256;
            int kr = idx >> 6, nv = (idx & 63) * 4;
            float4 t;
            t.x = f2tf32(pb[it].x); t.y = f2tf32(pb[it].y);
            t.z = f2tf32(pb[it].z); t.w = f2tf32(pb[it].w);
            *reinterpret_cast<float4*>(&Bs[bswz(kr, nv)]) = t;
        }
        __syncthreads();
        if (k0 + BK < kmax) {
            #pragma unroll
            for (int it = 0; it < 2; it++) {
                int idx = tid + it * 256;
                pa[it] = *reinterpret_cast<const float4*>(
                    &A[(size_t)(row0 + (idx >> 2)) * K + k0 + BK + (idx & 3) * 4]);
            }
            #pragma unroll
            for (int it = 0; it < 4; it++) {
                int idx = tid + it * 256;
                pb[it] = *reinterpret_cast<const float4*>(
                    &Bv[(size_t)(k0 + BK + (idx >> 6)) * N + col0 + (idx & 63) * 4]);
            }
        }
        mma_tile_compute(As, Bs, c, lane, warpM, warpN);
    }

    #pragma unroll
    for (int mt = 0; mt < 4; mt++)
        #pragma unroll
        for (int nt = 0; nt < 8; nt++) {
            int r = row0 + warpM * 64 + mt * 16 + (lane >> 2);
            int cc = col0 + warpN * 64 + nt * 8 + (lane & 3) * 2;
            *reinterpret_cast<float2*>(&C[(size_t)r * N + cc]) =
                make_float2(c[mt][nt][0], c[mt][nt][1]);
            *reinterpret_cast<float2*>(&C[(size_t)(r + 8) * N + cc]) =
                make_float2(c[mt][nt][2], c[mt][nt][3]);
        }
}

// ---------------------------------------------------------------------------
extern "C" void kernel_launch(void* const* d_in, const int* in_sizes, int n_in,
                              void* d_out, int out_size) {
    const float* x  = (const float*)d_in[0];
    const float* Wq = (const float*)d_in[1];
    const float* Wk = (const float*)d_in[2];
    const float* Wv = (const float*)d_in[3];
    float* out = (float*)d_out;

    {
        dim3 grid(DIM / BN, MROWS / BM, 3);
        mm_qkv<<<grid, NTHREADS>>>(x, Wq, Wk, Wv);
    }
    {
        const float scale = 1.0f / sqrtf((float)DIM);
        dim3 grid(SEQ / BN, SEQ / BM, BATCH);
        mm_scores<<<grid, NTHREADS>>>(scale);
    }
    softmax_causal<<<BATCH * SEQ, NTHREADS>>>();
    {
        dim3 grid(DIM / BN, SEQ / BM, BATCH);
        mm_pv<<<grid, NTHREADS>>>(out);
    }
}